// round 4
// baseline (speedup 1.0000x reference)
#include <cuda_runtime.h>

#define BB 4
#define HH 64
#define WW 64
#define BANDS 128
#define CC 32
#define NPIX (BB*HH*WW)        // 16384
#define ALPHA 0.3f

// Scratch: intermediates for the two conv chains (2 MB each, 8 MB total)
__device__ float g_h1g[NPIX*CC];
__device__ float g_h1b[NPIX*CC];
__device__ float g_gamma[NPIX*CC];
__device__ float g_beta[NPIX*CC];

// One launch computes BOTH branches (gamma: blockIdx.y==0, beta: blockIdx.y==1).
// stage 0: psi -> h1{g,b};  stage 1: h1{g,b} -> {gamma,beta}
__global__ __launch_bounds__(128) void conv_pair_kernel(
    int stage,
    const float* __restrict__ psi,
    const float* __restrict__ wA, const float* __restrict__ bA,
    const float* __restrict__ wB, const float* __restrict__ bB)
{
    __shared__ float4 sW[9*CC*CC/4];   // 2304 float4 = 36 KB
    __shared__ float  sBias[CC];

    const int branch = blockIdx.y;
    const float* in;
    float* out;
    if (stage == 0) {
        in  = psi;
        out = branch ? g_h1b : g_h1g;
    } else {
        in  = branch ? g_h1b : g_h1g;
        out = branch ? g_beta : g_gamma;
    }
    const float* wsrc = branch ? wB : wA;
    const float* bsrc = branch ? bB : bA;

    // Cooperative weight stage into smem (vectorized)
    const float4* w4 = (const float4*)wsrc;
    #pragma unroll
    for (int i = threadIdx.x; i < 9*CC*CC/4; i += 128) sW[i] = w4[i];
    if (threadIdx.x < CC) sBias[threadIdx.x] = bsrc[threadIdx.x];
    __syncthreads();

    const unsigned p = blockIdx.x * 128u + threadIdx.x;   // pixel id
    const int b = p >> 12;            // / (64*64)
    const int y = (p >> 6) & 63;
    const int x = p & 63;

    float acc[CC];
    #pragma unroll
    for (int co = 0; co < CC; co++) acc[co] = sBias[co];

    #pragma unroll
    for (int ky = 0; ky < 3; ky++) {
        const int iy = y + ky - 1;
        if (iy < 0 || iy >= HH) continue;
        #pragma unroll
        for (int kx = 0; kx < 3; kx++) {
            const int ix = x + kx - 1;
            if (ix < 0 || ix >= WW) continue;
            const float4* ip = (const float4*)(in + (((b*HH) + iy)*WW + ix)*CC);
            float4 inv[8];
            #pragma unroll
            for (int j = 0; j < 8; j++) inv[j] = ip[j];
            const float* invf = (const float*)inv;
            const int kbase = (ky*3 + kx) * CC;
            #pragma unroll
            for (int ci = 0; ci < CC; ci++) {
                const float v = invf[ci];
                const float4* wr = &sW[(kbase + ci) * (CC/4)];
                #pragma unroll
                for (int j = 0; j < 8; j++) {
                    const float4 wv = wr[j];
                    acc[4*j+0] = fmaf(v, wv.x, acc[4*j+0]);
                    acc[4*j+1] = fmaf(v, wv.y, acc[4*j+1]);
                    acc[4*j+2] = fmaf(v, wv.z, acc[4*j+2]);
                    acc[4*j+3] = fmaf(v, wv.w, acc[4*j+3]);
                }
            }
        }
    }

    float4* op = (float4*)(out + p*CC);
    #pragma unroll
    for (int j = 0; j < 8; j++) {
        float a0 = acc[4*j+0], a1 = acc[4*j+1], a2 = acc[4*j+2], a3 = acc[4*j+3];
        float4 r;
        r.x = a0 > 0.f ? a0 : ALPHA*a0;
        r.y = a1 > 0.f ? a1 : ALPHA*a1;
        r.z = a2 > 0.f ? a2 : ALPHA*a2;
        r.w = a3 > 0.f ? a3 : ALPHA*a3;
        op[j] = r;
    }
}

// out[b,h,w,band,c] = x * gamma[b,h,w,c] + beta[b,h,w,c]
// float4 over c: total float4 = NPIX * BANDS * 8 = 16,777,216
__global__ __launch_bounds__(256) void film_kernel(
    const float4* __restrict__ x, float4* __restrict__ out)
{
    const unsigned long long i = (unsigned long long)blockIdx.x * 256u + threadIdx.x;
    const unsigned c4  = (unsigned)(i & 7u);
    const unsigned pix = (unsigned)(i >> 10);          // / (8 * 128)
    const unsigned gidx = pix*8u + c4;

    const float4 xv = x[i];
    const float4 gv = __ldg(((const float4*)g_gamma) + gidx);
    const float4 bv = __ldg(((const float4*)g_beta)  + gidx);

    float4 r;
    r.x = fmaf(xv.x, gv.x, bv.x);
    r.y = fmaf(xv.y, gv.y, bv.y);
    r.z = fmaf(xv.z, gv.z, bv.z);
    r.w = fmaf(xv.w, gv.w, bv.w);
    out[i] = r;
}

extern "C" void kernel_launch(void* const* d_in, const int* in_sizes, int n_in,
                              void* d_out, int out_size)
{
    const float* x   = (const float*)d_in[0];
    const float* psi = (const float*)d_in[1];
    const float* gw1 = (const float*)d_in[2];
    const float* gb1 = (const float*)d_in[3];
    const float* gw2 = (const float*)d_in[4];
    const float* gb2 = (const float*)d_in[5];
    const float* bw1 = (const float*)d_in[6];
    const float* bb1 = (const float*)d_in[7];
    const float* bw2 = (const float*)d_in[8];
    const float* bb2 = (const float*)d_in[9];

    dim3 gridc(NPIX/128, 2);
    conv_pair_kernel<<<gridc, 128>>>(0, psi, gw1, gb1, bw1, bb1);
    conv_pair_kernel<<<gridc, 128>>>(1, psi, gw2, gb2, bw2, bb2);

    const int n4 = NPIX * BANDS * (CC/4);     // 16,777,216 float4
    film_kernel<<<n4/256, 256>>>((const float4*)x, (float4*)d_out);
}